// round 12
// baseline (speedup 1.0000x reference)
#include <cuda_runtime.h>

#define NMAPS   128      // 4*32
#define H       480
#define W       640
#define GRID_N  10
#define CH      48
#define CW      64
#define CELLS   100
#define NTILES  (NMAPS * 50)   // dual-cell tiles: map*50 + ci*5 + j
#define INTMAX_ 0x7fffffff

__device__ float    g_cand_score[NMAPS * CELLS];
__device__ int      g_cand_gr[NMAPS * CELLS];
__device__ int      g_cand_gc[NMAPS * CELLS];
__device__ unsigned g_count[NMAPS];   // never reset: mod-100 detects last arrival per map per launch

// larger value wins; exact tie -> smaller flat index (first occurrence, like jnp.argmax)
__device__ __forceinline__ void combine(float& bv, int& bi, float v, int i) {
    if (v > bv || (v == bv && i < bi)) { bv = v; bi = i; }
}
__device__ __forceinline__ float vmax4(float4 v) {
    return fmaxf(fmaxf(v.x, v.y), fmaxf(v.z, v.w));
}
__device__ __forceinline__ int selidx(float4 v, float m, int f) {
    int a = (v.x == m) ? f     : INTMAX_;
    int b = (v.y == m) ? f + 1 : INTMAX_;
    int c = (v.z == m) ? f + 2 : INTMAX_;
    int d = (v.w == m) ? f + 3 : INTMAX_;
    return min(min(a, b), min(c, d));
}

// 6 independent coalesced float4 loads for one dual-cell tile (48 rows x 128 cols)
__device__ __forceinline__ void load_tile(const float* __restrict__ s, int tile,
                                          int w, int lq, float4 v[6]) {
    const int map = tile / 50;
    const int rem = tile - map * 50;
    const int ci  = rem / 5;
    const int j   = rem - ci * 5;
    const float4* p = reinterpret_cast<const float4*>(s + (size_t)map * (H * W))
                    + (size_t)(ci * CH + w) * (W / 4) + j * 32 + lq;
    const int rowstep = 8 * (W / 4);
    #pragma unroll
    for (int it = 0; it < 6; ++it) v[it] = p[it * rowstep];
}

// Persistent CTAs: grid-stride over 6400 dual-cell tiles, next-tile register prefetch.
__global__ __launch_bounds__(256, 4)
void persistent_argmax_topk_kernel(const float* __restrict__ s, float* __restrict__ out, int top_n) {
    const int tid  = threadIdx.x;
    const int w    = tid >> 5;     // warp = row within 8-row band
    const int lq   = tid & 31;     // float4 col within 128-col tile
    const int half = lq >> 4;      // 0 -> left cell, 1 -> right cell
    const int ccol = lq & 15;      // float4 col within the cell

    __shared__ float sv[2][8];
    __shared__ int   si[2][8];
    __shared__ int   s_last;

    int tile = blockIdx.x;
    float4 cur[6];
    if (tile < NTILES) load_tile(s, tile, w, lq, cur);

    while (tile < NTILES) {
        const int next = tile + gridDim.x;
        float4 nxt[6];
        if (next < NTILES) load_tile(s, next, w, lq, nxt);   // prefetch: overlaps reduce below

        // ---- reduce current tile ----
        const int map = tile / 50;
        const int rem = tile - map * 50;
        const int ci  = rem / 5;
        const int j   = rem - ci * 5;
        const float* mbase = s + (size_t)map * (H * W);

        float tmax = fmaxf(fmaxf(fmaxf(vmax4(cur[0]), vmax4(cur[1])),
                                 fmaxf(vmax4(cur[2]), vmax4(cur[3]))),
                           fmaxf(vmax4(cur[4]), vmax4(cur[5])));
        const int fb = w * 64 + ccol * 4;   // flat idx within this thread's cell
        int bi = min(min(min(selidx(cur[0], tmax, fb),
                             selidx(cur[1], tmax, fb + 8 * 64)),
                         min(selidx(cur[2], tmax, fb + 16 * 64),
                             selidx(cur[3], tmax, fb + 24 * 64))),
                     min(selidx(cur[4], tmax, fb + 32 * 64),
                         selidx(cur[5], tmax, fb + 40 * 64)));
        float bv = tmax;

        // half-warp (width 16) reduce: per-cell partials at ccol==0
        #pragma unroll
        for (int off = 8; off > 0; off >>= 1) {
            float ov = __shfl_down_sync(0xffffffffu, bv, off, 16);
            int   oi = __shfl_down_sync(0xffffffffu, bi, off, 16);
            combine(bv, bi, ov, oi);
        }

        if (tid == 0) s_last = 0;
        if (ccol == 0) { sv[half][w] = bv; si[half][w] = bi; }
        __syncthreads();

        // threads 0,1 finalize the two cells of this tile
        if (tid < 2) {
            float fv = sv[tid][0];
            int   fi = si[tid][0];
            #pragma unroll
            for (int k = 1; k < 8; ++k) combine(fv, fi, sv[tid][k], si[tid][k]);
            const int cj   = 2 * j + tid;
            const int cidx = ci * GRID_N + cj;
            int lr2 = fi >> 6;
            int lc2 = fi & 63;
            int gr = ci * CH + lr2; gr = gr < 1 ? 1 : (gr > H - 2 ? H - 2 : gr);
            int gc = cj * CW + lc2; gc = gc < 1 ? 1 : (gc > W - 2 ? W - 2 : gc);
            // score is read at the CLAMPED coordinate (faithful to the reference)
            const int cell = map * CELLS + cidx;
            g_cand_score[cell] = mbase[gr * W + gc];
            g_cand_gr[cell]    = gr;
            g_cand_gc[cell]    = gc;
            __threadfence();                       // release: publish before counting
            unsigned old = atomicAdd(&g_count[map], 1u);
            if ((old % (unsigned)CELLS) == (unsigned)(CELLS - 1)) s_last = 1;
        }
        __syncthreads();

        // ---- the CTA that published this map's 100th candidate does its top-k ----
        if (s_last) {
            __shared__ unsigned long long keys[CELLS];
            __shared__ int   sgr[CELLS], sgc[CELLS];
            __shared__ float ssc[CELLS];

            __threadfence();                       // acquire
            if (tid < CELLS) {
                float sc = __ldcg(&g_cand_score[map * CELLS + tid]);
                int   gr = __ldcg(&g_cand_gr[map * CELLS + tid]);
                int   gc = __ldcg(&g_cand_gc[map * CELLS + tid]);
                unsigned u = __float_as_uint(sc);
                unsigned mono = (u & 0x80000000u) ? ~u : (u | 0x80000000u);
                keys[tid] = ((unsigned long long)mono << 32) | (unsigned)(CELLS - 1 - tid);
                sgr[tid] = gr; sgc[tid] = gc; ssc[tid] = sc;
            }
            __syncthreads();
            if (tid < CELLS) {
                const unsigned long long mk = keys[tid];
                int rank = 0;
                #pragma unroll 10
                for (int jj = 0; jj < CELLS; ++jj) rank += (keys[jj] > mk);
                if (rank < top_n) {
                    const int o = map * top_n + rank;
                    out[o]                     = (float)sgr[tid];   // x = row indices
                    out[NMAPS * top_n + o]     = (float)sgc[tid];   // y = col indices
                    out[2 * NMAPS * top_n + o] = ssc[tid];          // scores
                }
            }
        }
        __syncthreads();   // protect shared reuse before next iteration

        #pragma unroll
        for (int it = 0; it < 6; ++it) cur[it] = nxt[it];
        tile = next;
    }
}

extern "C" void kernel_launch(void* const* d_in, const int* in_sizes, int n_in,
                              void* d_out, int out_size) {
    const float* s = (const float*)d_in[0];
    int top_n = out_size / (3 * NMAPS);
    persistent_argmax_topk_kernel<<<592, 256>>>(s, (float*)d_out, top_n);  // 4 CTAs/SM, no waves
}

// round 15
// speedup vs baseline: 1.5427x; 1.5427x over previous
#include <cuda_runtime.h>

#define NMAPS   128      // 4*32
#define H       480
#define W       640
#define GRID_N  10
#define CH      48
#define CW      64
#define CELLS   100
#define INTMAX_ 0x7fffffff

__device__ float g_cand_score[NMAPS * CELLS];
__device__ int   g_cand_gr[NMAPS * CELLS];
__device__ int   g_cand_gc[NMAPS * CELLS];

// larger value wins; exact tie -> smaller flat index (first occurrence, like jnp.argmax)
__device__ __forceinline__ void combine(float& bv, int& bi, float v, int i) {
    if (v > bv || (v == bv && i < bi)) { bv = v; bi = i; }
}
__device__ __forceinline__ float vmax4(float4 v) {
    return fmaxf(fmaxf(v.x, v.y), fmaxf(v.z, v.w));
}
__device__ __forceinline__ int selidx(float4 v, float m, int f) {
    int a = (v.x == m) ? f     : INTMAX_;
    int b = (v.y == m) ? f + 1 : INTMAX_;
    int c = (v.z == m) ? f + 2 : INTMAX_;
    int d = (v.w == m) ? f + 3 : INTMAX_;
    return min(min(a, b), min(c, d));
}

// Pure streaming kernel: one CTA covers TWO horizontally adjacent cells
// (48 rows x 128 cols contiguous). NO atomics, NO fences — ordering comes
// from the kernel boundary. grid = 6400, block = 256.
__global__ __launch_bounds__(256)
void dualcell_argmax_kernel(const float* __restrict__ s) {
    const int blk  = blockIdx.x;                 // map*50 + ci*5 + j
    const int map  = blk / 50;
    const int rem  = blk - map * 50;
    const int ci   = rem / 5;
    const int j    = rem - ci * 5;               // double-cell column, covers cj=2j,2j+1

    const float* mbase = s + (size_t)map * (H * W);
    const float4* base4 = reinterpret_cast<const float4*>(mbase)
                        + (size_t)(ci * CH) * (W / 4) + j * 32;   // 128 floats = 32 float4

    const int tid = threadIdx.x;
    const int lr  = tid >> 5;      // warp id = starting row (warp covers one 512B row)
    const int lq  = tid & 31;      // float4 within 128-col double row
    const int half = lq >> 4;      // 0 -> cell 2j, 1 -> cell 2j+1
    const int ccol = lq & 15;      // float4 col within the cell

    const float4* p = base4 + lr * (W / 4) + lq;
    const int rowstep = 8 * (W / 4);

    // 6 independent 16B loads (rows lr, lr+8, ..., lr+40) -> MLP=6 per thread
    float4 v0 = p[0];
    float4 v1 = p[rowstep];
    float4 v2 = p[2 * rowstep];
    float4 v3 = p[3 * rowstep];
    float4 v4 = p[4 * rowstep];
    float4 v5 = p[5 * rowstep];

    float tmax = fmaxf(fmaxf(fmaxf(vmax4(v0), vmax4(v1)), fmaxf(vmax4(v2), vmax4(v3))),
                       fmaxf(vmax4(v4), vmax4(v5)));
    // flat idx within the thread's cell: (lr + 8*it)*64 + ccol*4 + k
    const int fb = lr * 64 + ccol * 4;
    int bi = min(min(min(selidx(v0, tmax, fb),
                         selidx(v1, tmax, fb + 8 * 64)),
                     min(selidx(v2, tmax, fb + 16 * 64),
                         selidx(v3, tmax, fb + 24 * 64))),
                 min(selidx(v4, tmax, fb + 32 * 64),
                     selidx(v5, tmax, fb + 40 * 64)));
    float bv = tmax;

    // half-warp (width 16) reduce: lanes 0 and 16 end with per-cell partials
    #pragma unroll
    for (int off = 8; off > 0; off >>= 1) {
        float ov = __shfl_down_sync(0xffffffffu, bv, off, 16);
        int   oi = __shfl_down_sync(0xffffffffu, bi, off, 16);
        combine(bv, bi, ov, oi);
    }

    __shared__ float sv[2][8];
    __shared__ int   si[2][8];
    if (ccol == 0) { sv[half][lr] = bv; si[half][lr] = bi; }
    __syncthreads();

    // threads 0,1 finalize the two cells; plain stores, no fences
    if (tid < 2) {
        float fv = sv[tid][0];
        int   fi = si[tid][0];
        #pragma unroll
        for (int k = 1; k < 8; ++k) combine(fv, fi, sv[tid][k], si[tid][k]);
        const int cj   = 2 * j + tid;
        const int cidx = ci * GRID_N + cj;
        int lr2 = fi >> 6;
        int lc2 = fi & 63;
        int gr = ci * CH + lr2; gr = gr < 1 ? 1 : (gr > H - 2 ? H - 2 : gr);
        int gc = cj * CW + lc2; gc = gc < 1 ? 1 : (gc > W - 2 ? W - 2 : gc);
        // score is read at the CLAMPED coordinate (faithful to the reference)
        const int cell = map * CELLS + cidx;
        g_cand_score[cell] = mbase[gr * W + gc];
        g_cand_gr[cell]    = gr;
        g_cand_gc[cell]    = gc;
    }
}

// Top-n of 100 candidates per map, jax.lax.top_k semantics:
// descending by value, ties broken by ascending candidate index.
__global__ __launch_bounds__(128) void topk_kernel(float* __restrict__ out, int top_n) {
    const int map = blockIdx.x;
    const int t   = threadIdx.x;

    __shared__ unsigned long long keys[CELLS];

    float myscore = 0.f;
    int   mygr = 0, mygc = 0;
    unsigned long long mykey = 0;

    if (t < CELLS) {
        myscore = g_cand_score[map * CELLS + t];
        mygr    = g_cand_gr[map * CELLS + t];
        mygc    = g_cand_gc[map * CELLS + t];
        unsigned u = __float_as_uint(myscore);
        unsigned mono = (u & 0x80000000u) ? ~u : (u | 0x80000000u);  // order-preserving
        mykey = ((unsigned long long)mono << 32) | (unsigned)(CELLS - 1 - t);
        keys[t] = mykey;
    }
    __syncthreads();

    if (t < CELLS) {
        int rank = 0;
        #pragma unroll 10
        for (int jj = 0; jj < CELLS; ++jj) rank += (keys[jj] > mykey);
        if (rank < top_n) {
            const int o = map * top_n + rank;
            out[o]                     = (float)mygr;   // x = row indices
            out[NMAPS * top_n + o]     = (float)mygc;   // y = col indices
            out[2 * NMAPS * top_n + o] = myscore;       // scores
        }
    }
}

extern "C" void kernel_launch(void* const* d_in, const int* in_sizes, int n_in,
                              void* d_out, int out_size) {
    const float* s = (const float*)d_in[0];
    int top_n = out_size / (3 * NMAPS);
    dualcell_argmax_kernel<<<NMAPS * GRID_N * (GRID_N / 2), 256>>>(s);
    topk_kernel<<<NMAPS, 128>>>((float*)d_out, top_n);
}

// round 16
// speedup vs baseline: 1.5698x; 1.0176x over previous
#include <cuda_runtime.h>

#define NMAPS   128      // 4*32
#define H       480
#define W       640
#define GRID_N  10
#define CH      48
#define CW      64
#define CELLS   100
#define INTMAX_ 0x7fffffff

__device__ float g_cand_score[NMAPS * CELLS];
__device__ int   g_cand_gr[NMAPS * CELLS];
__device__ int   g_cand_gc[NMAPS * CELLS];

// larger value wins; exact tie -> smaller flat index (first occurrence, like jnp.argmax)
__device__ __forceinline__ void combine(float& bv, int& bi, float v, int i) {
    if (v > bv || (v == bv && i < bi)) { bv = v; bi = i; }
}
__device__ __forceinline__ float vmax4(float4 v) {
    return fmaxf(fmaxf(v.x, v.y), fmaxf(v.z, v.w));
}
__device__ __forceinline__ int selidx(float4 v, float m, int f) {
    int a = (v.x == m) ? f     : INTMAX_;
    int b = (v.y == m) ? f + 1 : INTMAX_;
    int c = (v.z == m) ? f + 2 : INTMAX_;
    int d = (v.w == m) ? f + 3 : INTMAX_;
    return min(min(a, b), min(c, d));
}

// Pure streaming kernel: one CTA covers TWO horizontally adjacent cells
// (48 rows x 128 cols contiguous). grid = 6400, block = 256.
__global__ __launch_bounds__(256)
void dualcell_argmax_kernel(const float* __restrict__ s) {
    const int blk  = blockIdx.x;                 // map*50 + ci*5 + j
    const int map  = blk / 50;
    const int rem  = blk - map * 50;
    const int ci   = rem / 5;
    const int j    = rem - ci * 5;               // double-cell column, covers cj=2j,2j+1

    const float* mbase = s + (size_t)map * (H * W);
    const float4* base4 = reinterpret_cast<const float4*>(mbase)
                        + (size_t)(ci * CH) * (W / 4) + j * 32;   // 128 floats = 32 float4

    const int tid = threadIdx.x;
    const int lr  = tid >> 5;      // warp id = starting row (warp covers one 512B row)
    const int lq  = tid & 31;      // float4 within 128-col double row
    const int half = lq >> 4;      // 0 -> cell 2j, 1 -> cell 2j+1
    const int ccol = lq & 15;      // float4 col within the cell

    const float4* p = base4 + lr * (W / 4) + lq;
    const int rowstep = 8 * (W / 4);

    // 6 independent 16B loads (rows lr, lr+8, ..., lr+40) -> MLP=6 per thread
    float4 v0 = p[0];
    float4 v1 = p[rowstep];
    float4 v2 = p[2 * rowstep];
    float4 v3 = p[3 * rowstep];
    float4 v4 = p[4 * rowstep];
    float4 v5 = p[5 * rowstep];

    float tmax = fmaxf(fmaxf(fmaxf(vmax4(v0), vmax4(v1)), fmaxf(vmax4(v2), vmax4(v3))),
                       fmaxf(vmax4(v4), vmax4(v5)));
    // flat idx within the thread's cell: (lr + 8*it)*64 + ccol*4 + k
    const int fb = lr * 64 + ccol * 4;
    int bi = min(min(min(selidx(v0, tmax, fb),
                         selidx(v1, tmax, fb + 8 * 64)),
                     min(selidx(v2, tmax, fb + 16 * 64),
                         selidx(v3, tmax, fb + 24 * 64))),
                 min(selidx(v4, tmax, fb + 32 * 64),
                     selidx(v5, tmax, fb + 40 * 64)));
    float bv = tmax;

    // half-warp (width 16) reduce: lanes 0 and 16 end with per-cell partials
    #pragma unroll
    for (int off = 8; off > 0; off >>= 1) {
        float ov = __shfl_down_sync(0xffffffffu, bv, off, 16);
        int   oi = __shfl_down_sync(0xffffffffu, bi, off, 16);
        combine(bv, bi, ov, oi);
    }

    __shared__ float sv[2][8];
    __shared__ int   si[2][8];
    if (ccol == 0) { sv[half][lr] = bv; si[half][lr] = bi; }
    __syncthreads();

    // threads 0,1 finalize the two cells; plain stores
    if (tid < 2) {
        float fv = sv[tid][0];
        int   fi = si[tid][0];
        #pragma unroll
        for (int k = 1; k < 8; ++k) combine(fv, fi, sv[tid][k], si[tid][k]);
        const int cj   = 2 * j + tid;
        const int cidx = ci * GRID_N + cj;
        int lr2 = fi >> 6;
        int lc2 = fi & 63;
        int gr = ci * CH + lr2; gr = gr < 1 ? 1 : (gr > H - 2 ? H - 2 : gr);
        int gc = cj * CW + lc2; gc = gc < 1 ? 1 : (gc > W - 2 ? W - 2 : gc);
        // score is read at the CLAMPED coordinate (faithful to the reference)
        const int cell = map * CELLS + cidx;
        g_cand_score[cell] = mbase[gr * W + gc];
        g_cand_gr[cell]    = gr;
        g_cand_gc[cell]    = gc;
    }
    __syncthreads();   // all candidate stores issued before the PDL trigger
    // PDL: signal the dependent topk kernel that this CTA's writes are done
    cudaTriggerProgrammaticLaunchCompletion();
}

// Top-n of 100 candidates per map, jax.lax.top_k semantics. Launched with
// programmatic stream serialization: starts early, waits on the primary grid.
__global__ __launch_bounds__(128) void topk_kernel(float* __restrict__ out, int top_n) {
    const int map = blockIdx.x;
    const int t   = threadIdx.x;

    // Wait until all primary CTAs have triggered (their g_cand writes visible)
    cudaGridDependencySynchronize();

    __shared__ unsigned long long keys[CELLS];

    float myscore = 0.f;
    int   mygr = 0, mygc = 0;
    unsigned long long mykey = 0;

    if (t < CELLS) {
        myscore = g_cand_score[map * CELLS + t];
        mygr    = g_cand_gr[map * CELLS + t];
        mygc    = g_cand_gc[map * CELLS + t];
        unsigned u = __float_as_uint(myscore);
        unsigned mono = (u & 0x80000000u) ? ~u : (u | 0x80000000u);  // order-preserving
        mykey = ((unsigned long long)mono << 32) | (unsigned)(CELLS - 1 - t);
        keys[t] = mykey;
    }
    __syncthreads();

    if (t < CELLS) {
        int rank = 0;
        #pragma unroll 10
        for (int jj = 0; jj < CELLS; ++jj) rank += (keys[jj] > mykey);
        if (rank < top_n) {
            const int o = map * top_n + rank;
            out[o]                     = (float)mygr;   // x = row indices
            out[NMAPS * top_n + o]     = (float)mygc;   // y = col indices
            out[2 * NMAPS * top_n + o] = myscore;       // scores
        }
    }
}

extern "C" void kernel_launch(void* const* d_in, const int* in_sizes, int n_in,
                              void* d_out, int out_size) {
    const float* s = (const float*)d_in[0];
    int top_n = out_size / (3 * NMAPS);

    dualcell_argmax_kernel<<<NMAPS * GRID_N * (GRID_N / 2), 256>>>(s);

    // Secondary launch with PDL: may start while the primary drains; its
    // cudaGridDependencySynchronize() provides the ordering.
    cudaLaunchConfig_t cfg = {};
    cfg.gridDim  = dim3(NMAPS, 1, 1);
    cfg.blockDim = dim3(128, 1, 1);
    cfg.dynamicSmemBytes = 0;
    cfg.stream = (cudaStream_t)0;   // legacy default stream (same as <<<>>> above)
    cudaLaunchAttribute attr[1];
    attr[0].id = cudaLaunchAttributeProgrammaticStreamSerialization;
    attr[0].val.programmaticStreamSerializationAllowed = 1;
    cfg.attrs = attr;
    cfg.numAttrs = 1;
    cudaLaunchKernelEx(&cfg, topk_kernel, (float*)d_out, top_n);
}